// round 3
// baseline (speedup 1.0000x reference)
#include <cuda_runtime.h>
#include <cuda_bf16.h>
#include <cstdint>
#include <cstddef>

// ---------------------------------------------------------------------------
// Problem constants
// ---------------------------------------------------------------------------
#define NN 8192
#define MM 8192
#define DD 256
#define CC 128
#define HH 128
#define NROWS (NN + MM)          // 16384 stacked rows

// ---------------------------------------------------------------------------
// Static device scratch (no allocation allowed)
// ---------------------------------------------------------------------------
__device__ __nv_bfloat16 g_norm[(size_t)NROWS * DD];   // normalized x1 | x2  (8 MB)
__device__ __nv_bfloat16 g_Xb  [(size_t)NROWS * DD];   // raw x1 | x2 bf16    (8 MB)
__device__ __nv_bfloat16 g_WcT [CC * DD];              // Wc^T  [128][256]
__device__ __nv_bfloat16 g_W1T [HH * (2 * CC)];        // W1^T  [128][256]
__device__ __nv_bfloat16 g_W2T [HH * HH];              // W2^T  [128][128]
__device__ __nv_bfloat16 g_xc  [(size_t)NROWS * CC];   // compressor out (4 MB)
__device__ __nv_bfloat16 g_Z   [(size_t)NROWS * (2*CC)]; // critic inputs (8 MB)
__device__ __nv_bfloat16 g_H1  [(size_t)NROWS * HH];
__device__ __nv_bfloat16 g_H2  [(size_t)NROWS * HH];
__device__ float         g_T   [NROWS];
__device__ float         g_const;

// ---------------------------------------------------------------------------
// helpers
// ---------------------------------------------------------------------------
__device__ __forceinline__ uint32_t smem_u32(const void* p) {
    return static_cast<uint32_t>(__cvta_generic_to_shared(p));
}

__device__ __forceinline__ void ldsm_x4(uint32_t& r0, uint32_t& r1,
                                        uint32_t& r2, uint32_t& r3,
                                        uint32_t addr) {
    asm volatile("ldmatrix.sync.aligned.m8n8.x4.shared.b16 {%0,%1,%2,%3}, [%4];\n"
                 : "=r"(r0), "=r"(r1), "=r"(r2), "=r"(r3) : "r"(addr));
}

__device__ __forceinline__ void mma16816(float* d, const uint32_t* a,
                                         uint32_t b0, uint32_t b1) {
    asm volatile(
        "mma.sync.aligned.m16n8k16.row.col.f32.bf16.bf16.f32 "
        "{%0,%1,%2,%3}, {%4,%5,%6,%7}, {%8,%9}, {%0,%1,%2,%3};\n"
        : "+f"(d[0]), "+f"(d[1]), "+f"(d[2]), "+f"(d[3])
        : "r"(a[0]), "r"(a[1]), "r"(a[2]), "r"(a[3]), "r"(b0), "r"(b1));
}

__device__ __forceinline__ void cp_async16(uint32_t dst, const void* src) {
    asm volatile("cp.async.cg.shared.global [%0], [%1], 16;\n"
                 :: "r"(dst), "l"(src));
}
#define CP_COMMIT()  asm volatile("cp.async.commit_group;\n" ::: "memory")
#define CP_WAIT(N)   asm volatile("cp.async.wait_group %0;\n" :: "n"(N) : "memory")

// ---------------------------------------------------------------------------
// Kernel 1: row normalize (for distances) + raw bf16 copy (for compressor)
// ---------------------------------------------------------------------------
__global__ void prep_kernel(const float* __restrict__ x1,
                            const float* __restrict__ x2) {
    int row = blockIdx.x;
    int t   = threadIdx.x;
    const float* x = (row < NN) ? (x1 + (size_t)row * DD)
                                : (x2 + (size_t)(row - NN) * DD);
    float v = x[t];
    float s = v * v;
    #pragma unroll
    for (int o = 16; o; o >>= 1) s += __shfl_xor_sync(0xffffffffu, s, o);
    __shared__ float ws[8];
    if ((t & 31) == 0) ws[t >> 5] = s;
    __syncthreads();
    float tot = 0.f;
    #pragma unroll
    for (int i = 0; i < 8; i++) tot += ws[i];
    float inv = 1.0f / fmaxf(sqrtf(tot), 1e-8f);
    g_norm[(size_t)row * DD + t] = __float2bfloat16(v * inv);
    g_Xb  [(size_t)row * DD + t] = __float2bfloat16(v);
}

// ---------------------------------------------------------------------------
// Kernel 2: transpose Wc, W1, W2 into bf16 [n][k] layouts
// ---------------------------------------------------------------------------
__global__ void transp_kernel(const float* __restrict__ Wc,
                              const float* __restrict__ W1,
                              const float* __restrict__ W2) {
    int idx = blockIdx.x * 256 + threadIdx.x;
    if (idx < CC * DD) {
        int j = idx >> 8, k = idx & 255;
        g_WcT[idx] = __float2bfloat16(Wc[k * CC + j]);
    } else if (idx < 2 * CC * DD) {
        int o = idx - CC * DD;
        int j = o >> 8, k = o & 255;
        g_W1T[o] = __float2bfloat16(W1[k * HH + j]);
    } else {
        int o = idx - 2 * CC * DD;
        if (o < HH * HH) {
            int j = o >> 7, k = o & 127;
            g_W2T[o] = __float2bfloat16(W2[k * HH + j]);
        }
    }
}

// ---------------------------------------------------------------------------
// Small critic GEMMs (mma.sync), C = A @ B^T
//   MODE 1: XC  A=g_Xb  B=g_WcT  out = acc + bc       (bf16)
//   MODE 2: H1  A=g_Z   B=g_W1T  out = relu(acc+b1)   (bf16)
//   MODE 3: H2  A=g_H1  B=g_W2T  out = relu(acc+b2)   (bf16)
// ---------------------------------------------------------------------------
#define BM 128
#define BN 128
#define BKs 64

template <int MODE>
__global__ void __launch_bounds__(256, 2)
gemm_k(const float* __restrict__ bias) {
    constexpr int K = (MODE == 3) ? 128 : 256;

    const __nv_bfloat16* A;
    const __nv_bfloat16* B;
    if      (MODE == 1) { A = g_Xb;   B = g_WcT; }
    else if (MODE == 2) { A = g_Z;    B = g_W1T; }
    else                { A = g_H1;   B = g_W2T; }

    __shared__ __nv_bfloat16 sA[BM * BKs];
    __shared__ __nv_bfloat16 sB[BN * BKs];

    const int bm   = blockIdx.y * BM;
    const int bn   = blockIdx.x * BN;
    const int t    = threadIdx.x;
    const int warp = t >> 5;
    const int lane = t & 31;
    const int wm   = (warp >> 1) * 32;
    const int wn   = (warp & 1) * 64;

    float acc[2][8][4];
    #pragma unroll
    for (int i = 0; i < 2; i++)
        #pragma unroll
        for (int j = 0; j < 8; j++)
            #pragma unroll
            for (int r = 0; r < 4; r++) acc[i][j][r] = 0.f;

    const uint32_t sAb = smem_u32(sA);
    const uint32_t sBb = smem_u32(sB);

    for (int kc = 0; kc < K; kc += BKs) {
        #pragma unroll
        for (int i = 0; i < 4; i++) {
            int idx = t + i * 256;
            int row = idx >> 3;
            int ch  = idx & 7;
            int sw  = (ch ^ (row & 7)) * 8;
            uint4 va = *reinterpret_cast<const uint4*>(
                A + (size_t)(bm + row) * K + kc + ch * 8);
            *reinterpret_cast<uint4*>(sA + row * BKs + sw) = va;
            uint4 vb = *reinterpret_cast<const uint4*>(
                B + (size_t)(bn + row) * K + kc + ch * 8);
            *reinterpret_cast<uint4*>(sB + row * BKs + sw) = vb;
        }
        __syncthreads();

        #pragma unroll
        for (int ks = 0; ks < BKs / 16; ks++) {
            uint32_t a[2][4];
            #pragma unroll
            for (int mt = 0; mt < 2; mt++) {
                int r = wm + mt * 16 + (lane & 15);
                int c = (ks * 2 + (lane >> 4)) ^ (r & 7);
                ldsm_x4(a[mt][0], a[mt][1], a[mt][2], a[mt][3],
                        sAb + (uint32_t)(r * BKs + c * 8) * 2u);
            }
            uint32_t b[4][4];
            #pragma unroll
            for (int bt = 0; bt < 4; bt++) {
                int nr = wn + bt * 16 + ((lane >> 4) * 8) + (lane & 7);
                int kh = (lane >> 3) & 1;
                int c  = (ks * 2 + kh) ^ (nr & 7);
                ldsm_x4(b[bt][0], b[bt][1], b[bt][2], b[bt][3],
                        sBb + (uint32_t)(nr * BKs + c * 8) * 2u);
            }
            #pragma unroll
            for (int mt = 0; mt < 2; mt++)
                #pragma unroll
                for (int nt = 0; nt < 8; nt++)
                    mma16816(acc[mt][nt], a[mt],
                             b[nt >> 1][(nt & 1) * 2],
                             b[nt >> 1][(nt & 1) * 2 + 1]);
        }
        __syncthreads();
    }

    __nv_bfloat16* ob = (MODE == 1) ? g_xc : (MODE == 2) ? g_H1 : g_H2;

    #pragma unroll
    for (int mt = 0; mt < 2; mt++) {
        #pragma unroll
        for (int nt = 0; nt < 8; nt++) {
            int row = bm + wm + mt * 16 + (lane >> 2);
            int col = bn + wn + nt * 8 + (lane & 3) * 2;
            float* c = acc[mt][nt];
            float b0 = bias[col], b1 = bias[col + 1];
            float v0 = c[0] + b0, v1 = c[1] + b1;
            float v2 = c[2] + b0, v3 = c[3] + b1;
            if (MODE >= 2) {
                v0 = fmaxf(v0, 0.f); v1 = fmaxf(v1, 0.f);
                v2 = fmaxf(v2, 0.f); v3 = fmaxf(v3, 0.f);
            }
            __nv_bfloat162 h0, h1;
            h0.x = __float2bfloat16(v0); h0.y = __float2bfloat16(v1);
            h1.x = __float2bfloat16(v2); h1.y = __float2bfloat16(v3);
            *reinterpret_cast<__nv_bfloat162*>(ob + (size_t)row * CC + col)       = h0;
            *reinterpret_cast<__nv_bfloat162*>(ob + (size_t)(row + 8) * CC + col) = h1;
        }
    }
}

// ---------------------------------------------------------------------------
// Kernel 4: build critic inputs; warp per row, 16B per lane
// ---------------------------------------------------------------------------
__global__ void gather_kernel(const int* __restrict__ perm) {
    int row  = blockIdx.x * 8 + (threadIdx.x >> 5);
    int lane = threadIdx.x & 31;
    int i    = row & (NN - 1);
    int src2 = (row >= NN) ? perm[i] : i;

    const uint4* s1 = reinterpret_cast<const uint4*>(g_xc + (size_t)i * CC);
    const uint4* s2 = reinterpret_cast<const uint4*>(g_xc + (size_t)(NN + src2) * CC);
    uint4* dst = reinterpret_cast<uint4*>(g_Z + (size_t)row * 256);

    if (lane < 16) dst[lane] = s1[lane];
    else           dst[lane] = s2[lane - 16];
}

// ---------------------------------------------------------------------------
// Kernel 7: t = H2 @ W3 + b3  (warp per row)
// ---------------------------------------------------------------------------
__global__ void tdot_kernel(const float* __restrict__ W3,
                            const float* __restrict__ b3) {
    int row  = blockIdx.x * 8 + (threadIdx.x >> 5);
    int lane = threadIdx.x & 31;
    const __nv_bfloat16* h = g_H2 + (size_t)row * HH;
    float s = 0.f;
    #pragma unroll
    for (int i = 0; i < 4; i++) {
        int k = lane + i * 32;
        s += __bfloat162float(h[k]) * W3[k];
    }
    #pragma unroll
    for (int o = 16; o; o >>= 1) s += __shfl_xor_sync(0xffffffffu, s, o);
    if (lane == 0) g_T[row] = s + b3[0];
}

// ---------------------------------------------------------------------------
// Kernel 8: deterministic reduction -> g_const = 1 + 0.01 * mi
// ---------------------------------------------------------------------------
__global__ void reduce_kernel() {
    int t = threadIdx.x;
    float s1 = 0.f, s2 = 0.f;
    for (int i = t; i < NN; i += 256) {
        s1 += g_T[i];
        s2 += expf(g_T[NN + i]);
    }
    __shared__ float a1[256], a2[256];
    a1[t] = s1; a2[t] = s2;
    __syncthreads();
    for (int st = 128; st; st >>= 1) {
        if (t < st) { a1[t] += a1[t + st]; a2[t] += a2[t + st]; }
        __syncthreads();
    }
    if (t == 0) {
        float mi = a1[0] / (float)NN - (a2[0] / (float)NN + logf(2.0f));
        g_const = 1.0f + 0.01f * mi;
    }
}

// ---------------------------------------------------------------------------
// Kernel 9: DIST.  out[i][j] = g_const - <x1n_i, x2n_j>
// CTA tile 128x256, BK=32, 3-stage cp.async pipeline, 8 warps (2m x 4n),
// warp tile 64x64.  Padded SMEM rows (stride 40 bf16 = 80B) -> conflict-free
// ldmatrix without XOR swizzle.
// ---------------------------------------------------------------------------
#define DBM 128
#define DBN 256
#define DBK 32
#define STAGES 3
#define ASTRIDE 40                          // bf16 elements per SMEM row
#define A_STAGE_B (DBM * ASTRIDE * 2)       // 10240 B
#define B_STAGE_B (DBN * ASTRIDE * 2)       // 20480 B
#define STAGE_B   (A_STAGE_B + B_STAGE_B)   // 30720 B
#define DSMEM_TOTAL (STAGES * STAGE_B)      // 92160 B

__global__ void __launch_bounds__(256, 1)
dist_kernel(float* __restrict__ outf) {
    extern __shared__ char smem[];
    const uint32_t sb = smem_u32(smem);

    const int t    = threadIdx.x;
    const int warp = t >> 5;
    const int lane = t & 31;
    const int bm   = blockIdx.y * DBM;
    const int bn   = blockIdx.x * DBN;
    const int wm   = (warp >> 2) * 64;      // 0 | 64
    const int wn   = (warp & 3) * 64;       // 0 | 64 | 128 | 192

    const __nv_bfloat16* A = g_norm;                    // [8192][256]
    const __nv_bfloat16* B = g_norm + (size_t)NN * DD;  // [8192][256]

    float acc[4][8][4];
    #pragma unroll
    for (int i = 0; i < 4; i++)
        #pragma unroll
        for (int j = 0; j < 8; j++)
            #pragma unroll
            for (int r = 0; r < 4; r++) acc[i][j][r] = 0.f;

    // ---- stage loader: A 128x32 (2 chunks/thr), B 256x32 (4 chunks/thr) ----
    auto load_stage = [&](int s, int kc) {
        uint32_t base = sb + s * STAGE_B;
        #pragma unroll
        for (int i = 0; i < 2; i++) {
            int idx = t + i * 256;          // 0..511
            int row = idx >> 2;
            int ch  = idx & 3;
            cp_async16(base + row * 80 + ch * 16,
                       A + (size_t)(bm + row) * DD + kc + ch * 8);
        }
        #pragma unroll
        for (int i = 0; i < 4; i++) {
            int idx = t + i * 256;          // 0..1023
            int row = idx >> 2;
            int ch  = idx & 3;
            cp_async16(base + A_STAGE_B + row * 80 + ch * 16,
                       B + (size_t)(bn + row) * DD + kc + ch * 8);
        }
    };

    // ---- prologue: fill STAGES-1 stages ----
    #pragma unroll
    for (int s = 0; s < STAGES - 1; s++) {
        load_stage(s, s * DBK);
        CP_COMMIT();
    }

    const int NCHUNK = DD / DBK;            // 8
    #pragma unroll 1
    for (int c = 0; c < NCHUNK; c++) {
        CP_WAIT(STAGES - 2);                // stage c resident
        __syncthreads();

        // issue next stage loads (overlap with compute below)
        if (c + STAGES - 1 < NCHUNK)
            load_stage((c + STAGES - 1) % STAGES, (c + STAGES - 1) * DBK);
        CP_COMMIT();                        // empty group ok, keeps count uniform

        const uint32_t aS = sb + (c % STAGES) * STAGE_B;
        const uint32_t bS = aS + A_STAGE_B;

        #pragma unroll
        for (int ks = 0; ks < 2; ks++) {    // two k16 steps in BK=32
            uint32_t a[4][4];
            #pragma unroll
            for (int mt = 0; mt < 4; mt++) {
                int r  = wm + mt * 16 + (lane & 15);
                int kb = ks * 16 + (lane >> 4) * 8;
                ldsm_x4(a[mt][0], a[mt][1], a[mt][2], a[mt][3],
                        aS + (uint32_t)(r * ASTRIDE + kb) * 2u);
            }
            uint32_t b[4][4];
            #pragma unroll
            for (int bt = 0; bt < 4; bt++) {
                int nr = wn + bt * 16 + ((lane >> 4) * 8) + (lane & 7);
                int kb = ks * 16 + ((lane >> 3) & 1) * 8;
                ldsm_x4(b[bt][0], b[bt][1], b[bt][2], b[bt][3],
                        bS + (uint32_t)(nr * ASTRIDE + kb) * 2u);
            }
            #pragma unroll
            for (int mt = 0; mt < 4; mt++)
                #pragma unroll
                for (int nt = 0; nt < 8; nt++)
                    mma16816(acc[mt][nt], a[mt],
                             b[nt >> 1][(nt & 1) * 2],
                             b[nt >> 1][(nt & 1) * 2 + 1]);
        }
    }

    // ---- epilogue: out = g_const - acc ----
    const float cadd = g_const;
    #pragma unroll
    for (int mt = 0; mt < 4; mt++) {
        #pragma unroll
        for (int nt = 0; nt < 8; nt++) {
            int row = bm + wm + mt * 16 + (lane >> 2);
            int col = bn + wn + nt * 8 + (lane & 3) * 2;
            float* c = acc[mt][nt];
            float2 v0 = make_float2(cadd - c[0], cadd - c[1]);
            float2 v1 = make_float2(cadd - c[2], cadd - c[3]);
            *reinterpret_cast<float2*>(outf + (size_t)row * MM + col)       = v0;
            *reinterpret_cast<float2*>(outf + (size_t)(row + 8) * MM + col) = v1;
        }
    }
}

// ---------------------------------------------------------------------------
// kernel_launch
// ---------------------------------------------------------------------------
extern "C" void kernel_launch(void* const* d_in, const int* in_sizes, int n_in,
                              void* d_out, int out_size) {
    const float* x1   = (const float*)d_in[0];
    const float* x2   = (const float*)d_in[1];
    const float* Wc   = (const float*)d_in[2];
    const float* bc   = (const float*)d_in[3];
    const float* W1   = (const float*)d_in[4];
    const float* b1   = (const float*)d_in[5];
    const float* W2   = (const float*)d_in[6];
    const float* b2   = (const float*)d_in[7];
    const float* W3   = (const float*)d_in[8];
    const float* b3   = (const float*)d_in[9];
    const int*   perm = (const int*)d_in[10];
    float* out = (float*)d_out;

    cudaFuncSetAttribute(dist_kernel,
                         cudaFuncAttributeMaxDynamicSharedMemorySize, DSMEM_TOTAL);

    // 1. normalize rows + raw bf16 copies
    prep_kernel<<<NROWS, 256>>>(x1, x2);
    // 2. weight transposes to bf16
    transp_kernel<<<(2 * CC * DD + HH * HH + 255) / 256, 256>>>(Wc, W1, W2);
    // 3. compressor: xc = x @ Wc + bc   [16384 x 128]
    gemm_k<1><<<dim3(1, NROWS / BM), 256>>>(bc);
    // 4. critic inputs (joint + shuffled)
    gather_kernel<<<NROWS / 8, 256>>>(perm);
    // 5. H1 = relu(Z @ W1 + b1)
    gemm_k<2><<<dim3(1, NROWS / BM), 256>>>(b1);
    // 6. H2 = relu(H1 @ W2 + b2)
    gemm_k<3><<<dim3(1, NROWS / BM), 256>>>(b2);
    // 7. t = H2 @ W3 + b3
    tdot_kernel<<<NROWS / 8, 256>>>(W3, b3);
    // 8. mi scalar -> g_const
    reduce_kernel<<<1, 256>>>();
    // 9. distances + lambda*mi
    dist_kernel<<<dim3(MM / DBN, NN / DBM), 256, DSMEM_TOTAL>>>(out);
}

// round 4
// speedup vs baseline: 1.3158x; 1.3158x over previous
#include <cuda_runtime.h>
#include <cuda_bf16.h>
#include <cstdint>
#include <cstddef>

// ---------------------------------------------------------------------------
// Problem constants
// ---------------------------------------------------------------------------
#define NN 8192
#define MM 8192
#define DD 256
#define CC 128
#define HH 128
#define NROWS (NN + MM)          // 16384 stacked rows

// ---------------------------------------------------------------------------
// Static device scratch (no allocation allowed)
// ---------------------------------------------------------------------------
__device__ __nv_bfloat16 g_norm[(size_t)NROWS * DD];   // normalized x1 | x2  (8 MB)
__device__ __nv_bfloat16 g_Xb  [(size_t)NROWS * DD];   // raw x1 | x2 bf16    (8 MB)
__device__ __nv_bfloat16 g_WcT [CC * DD];              // Wc^T  [128][256]
__device__ __nv_bfloat16 g_W1T [HH * (2 * CC)];        // W1^T  [128][256]
__device__ __nv_bfloat16 g_W2T [HH * HH];              // W2^T  [128][128]
__device__ __nv_bfloat16 g_xc  [(size_t)NROWS * CC];   // compressor out (4 MB)
__device__ __nv_bfloat16 g_Z   [(size_t)NROWS * (2*CC)]; // critic inputs (8 MB)
__device__ __nv_bfloat16 g_H1  [(size_t)NROWS * HH];
__device__ __nv_bfloat16 g_H2  [(size_t)NROWS * HH];
__device__ float         g_T   [NROWS];
__device__ float         g_const;

// ---------------------------------------------------------------------------
// helpers
// ---------------------------------------------------------------------------
__device__ __forceinline__ uint32_t smem_u32(const void* p) {
    return static_cast<uint32_t>(__cvta_generic_to_shared(p));
}

__device__ __forceinline__ void ldsm_x4(uint32_t& r0, uint32_t& r1,
                                        uint32_t& r2, uint32_t& r3,
                                        uint32_t addr) {
    asm volatile("ldmatrix.sync.aligned.m8n8.x4.shared.b16 {%0,%1,%2,%3}, [%4];\n"
                 : "=r"(r0), "=r"(r1), "=r"(r2), "=r"(r3) : "r"(addr));
}

__device__ __forceinline__ void mma16816(float* d, const uint32_t* a,
                                         uint32_t b0, uint32_t b1) {
    asm volatile(
        "mma.sync.aligned.m16n8k16.row.col.f32.bf16.bf16.f32 "
        "{%0,%1,%2,%3}, {%4,%5,%6,%7}, {%8,%9}, {%0,%1,%2,%3};\n"
        : "+f"(d[0]), "+f"(d[1]), "+f"(d[2]), "+f"(d[3])
        : "r"(a[0]), "r"(a[1]), "r"(a[2]), "r"(a[3]), "r"(b0), "r"(b1));
}

__device__ __forceinline__ void cp_async16(uint32_t dst, const void* src) {
    asm volatile("cp.async.cg.shared.global [%0], [%1], 16;\n"
                 :: "r"(dst), "l"(src));
}
#define CP_COMMIT()  asm volatile("cp.async.commit_group;\n" ::: "memory")
#define CP_WAIT(N)   asm volatile("cp.async.wait_group %0;\n" :: "n"(N) : "memory")

// ---------------------------------------------------------------------------
// Kernel 1: row normalize (for distances) + raw bf16 copy (for compressor)
// ---------------------------------------------------------------------------
__global__ void prep_kernel(const float* __restrict__ x1,
                            const float* __restrict__ x2) {
    int row = blockIdx.x;
    int t   = threadIdx.x;
    const float* x = (row < NN) ? (x1 + (size_t)row * DD)
                                : (x2 + (size_t)(row - NN) * DD);
    float v = x[t];
    float s = v * v;
    #pragma unroll
    for (int o = 16; o; o >>= 1) s += __shfl_xor_sync(0xffffffffu, s, o);
    __shared__ float ws[8];
    if ((t & 31) == 0) ws[t >> 5] = s;
    __syncthreads();
    float tot = 0.f;
    #pragma unroll
    for (int i = 0; i < 8; i++) tot += ws[i];
    float inv = 1.0f / fmaxf(sqrtf(tot), 1e-8f);
    g_norm[(size_t)row * DD + t] = __float2bfloat16(v * inv);
    g_Xb  [(size_t)row * DD + t] = __float2bfloat16(v);
}

// ---------------------------------------------------------------------------
// Kernel 2: transpose Wc, W1, W2 into bf16 [n][k] layouts
// ---------------------------------------------------------------------------
__global__ void transp_kernel(const float* __restrict__ Wc,
                              const float* __restrict__ W1,
                              const float* __restrict__ W2) {
    int idx = blockIdx.x * 256 + threadIdx.x;
    if (idx < CC * DD) {
        int j = idx >> 8, k = idx & 255;
        g_WcT[idx] = __float2bfloat16(Wc[k * CC + j]);
    } else if (idx < 2 * CC * DD) {
        int o = idx - CC * DD;
        int j = o >> 8, k = o & 255;
        g_W1T[o] = __float2bfloat16(W1[k * HH + j]);
    } else {
        int o = idx - 2 * CC * DD;
        if (o < HH * HH) {
            int j = o >> 7, k = o & 127;
            g_W2T[o] = __float2bfloat16(W2[k * HH + j]);
        }
    }
}

// ---------------------------------------------------------------------------
// Small critic GEMMs (mma.sync), C = A @ B^T
//   MODE 1: XC  A=g_Xb  B=g_WcT  out = acc + bc       (bf16)
//   MODE 2: H1  A=g_Z   B=g_W1T  out = relu(acc+b1)   (bf16)
//   MODE 3: H2  A=g_H1  B=g_W2T  out = relu(acc+b2)   (bf16)
// ---------------------------------------------------------------------------
#define BM 128
#define BN 128
#define BKs 64

template <int MODE>
__global__ void __launch_bounds__(256, 2)
gemm_k(const float* __restrict__ bias) {
    constexpr int K = (MODE == 3) ? 128 : 256;

    const __nv_bfloat16* A;
    const __nv_bfloat16* B;
    if      (MODE == 1) { A = g_Xb;   B = g_WcT; }
    else if (MODE == 2) { A = g_Z;    B = g_W1T; }
    else                { A = g_H1;   B = g_W2T; }

    __shared__ __nv_bfloat16 sA[BM * BKs];
    __shared__ __nv_bfloat16 sB[BN * BKs];

    const int bm   = blockIdx.y * BM;
    const int bn   = blockIdx.x * BN;
    const int t    = threadIdx.x;
    const int warp = t >> 5;
    const int lane = t & 31;
    const int wm   = (warp >> 1) * 32;
    const int wn   = (warp & 1) * 64;

    float acc[2][8][4];
    #pragma unroll
    for (int i = 0; i < 2; i++)
        #pragma unroll
        for (int j = 0; j < 8; j++)
            #pragma unroll
            for (int r = 0; r < 4; r++) acc[i][j][r] = 0.f;

    const uint32_t sAb = smem_u32(sA);
    const uint32_t sBb = smem_u32(sB);

    for (int kc = 0; kc < K; kc += BKs) {
        #pragma unroll
        for (int i = 0; i < 4; i++) {
            int idx = t + i * 256;
            int row = idx >> 3;
            int ch  = idx & 7;
            int sw  = (ch ^ (row & 7)) * 8;
            uint4 va = *reinterpret_cast<const uint4*>(
                A + (size_t)(bm + row) * K + kc + ch * 8);
            *reinterpret_cast<uint4*>(sA + row * BKs + sw) = va;
            uint4 vb = *reinterpret_cast<const uint4*>(
                B + (size_t)(bn + row) * K + kc + ch * 8);
            *reinterpret_cast<uint4*>(sB + row * BKs + sw) = vb;
        }
        __syncthreads();

        #pragma unroll
        for (int ks = 0; ks < BKs / 16; ks++) {
            uint32_t a[2][4];
            #pragma unroll
            for (int mt = 0; mt < 2; mt++) {
                int r = wm + mt * 16 + (lane & 15);
                int c = (ks * 2 + (lane >> 4)) ^ (r & 7);
                ldsm_x4(a[mt][0], a[mt][1], a[mt][2], a[mt][3],
                        sAb + (uint32_t)(r * BKs + c * 8) * 2u);
            }
            uint32_t b[4][4];
            #pragma unroll
            for (int bt = 0; bt < 4; bt++) {
                int nr = wn + bt * 16 + ((lane >> 4) * 8) + (lane & 7);
                int kh = (lane >> 3) & 1;
                int c  = (ks * 2 + kh) ^ (nr & 7);
                ldsm_x4(b[bt][0], b[bt][1], b[bt][2], b[bt][3],
                        sBb + (uint32_t)(nr * BKs + c * 8) * 2u);
            }
            #pragma unroll
            for (int mt = 0; mt < 2; mt++)
                #pragma unroll
                for (int nt = 0; nt < 8; nt++)
                    mma16816(acc[mt][nt], a[mt],
                             b[nt >> 1][(nt & 1) * 2],
                             b[nt >> 1][(nt & 1) * 2 + 1]);
        }
        __syncthreads();
    }

    __nv_bfloat16* ob = (MODE == 1) ? g_xc : (MODE == 2) ? g_H1 : g_H2;

    #pragma unroll
    for (int mt = 0; mt < 2; mt++) {
        #pragma unroll
        for (int nt = 0; nt < 8; nt++) {
            int row = bm + wm + mt * 16 + (lane >> 2);
            int col = bn + wn + nt * 8 + (lane & 3) * 2;
            float* c = acc[mt][nt];
            float b0 = bias[col], b1 = bias[col + 1];
            float v0 = c[0] + b0, v1 = c[1] + b1;
            float v2 = c[2] + b0, v3 = c[3] + b1;
            if (MODE >= 2) {
                v0 = fmaxf(v0, 0.f); v1 = fmaxf(v1, 0.f);
                v2 = fmaxf(v2, 0.f); v3 = fmaxf(v3, 0.f);
            }
            __nv_bfloat162 h0, h1;
            h0.x = __float2bfloat16(v0); h0.y = __float2bfloat16(v1);
            h1.x = __float2bfloat16(v2); h1.y = __float2bfloat16(v3);
            *reinterpret_cast<__nv_bfloat162*>(ob + (size_t)row * CC + col)       = h0;
            *reinterpret_cast<__nv_bfloat162*>(ob + (size_t)(row + 8) * CC + col) = h1;
        }
    }
}

// ---------------------------------------------------------------------------
// Kernel 4: build critic inputs; warp per row, 16B per lane
// ---------------------------------------------------------------------------
__global__ void gather_kernel(const int* __restrict__ perm) {
    int row  = blockIdx.x * 8 + (threadIdx.x >> 5);
    int lane = threadIdx.x & 31;
    int i    = row & (NN - 1);
    int src2 = (row >= NN) ? perm[i] : i;

    const uint4* s1 = reinterpret_cast<const uint4*>(g_xc + (size_t)i * CC);
    const uint4* s2 = reinterpret_cast<const uint4*>(g_xc + (size_t)(NN + src2) * CC);
    uint4* dst = reinterpret_cast<uint4*>(g_Z + (size_t)row * 256);

    if (lane < 16) dst[lane] = s1[lane];
    else           dst[lane] = s2[lane - 16];
}

// ---------------------------------------------------------------------------
// Kernel 7: t = H2 @ W3 + b3  (warp per row)
// ---------------------------------------------------------------------------
__global__ void tdot_kernel(const float* __restrict__ W3,
                            const float* __restrict__ b3) {
    int row  = blockIdx.x * 8 + (threadIdx.x >> 5);
    int lane = threadIdx.x & 31;
    const __nv_bfloat16* h = g_H2 + (size_t)row * HH;
    float s = 0.f;
    #pragma unroll
    for (int i = 0; i < 4; i++) {
        int k = lane + i * 32;
        s += __bfloat162float(h[k]) * W3[k];
    }
    #pragma unroll
    for (int o = 16; o; o >>= 1) s += __shfl_xor_sync(0xffffffffu, s, o);
    if (lane == 0) g_T[row] = s + b3[0];
}

// ---------------------------------------------------------------------------
// Kernel 8: deterministic reduction -> g_const = 1 + 0.01 * mi
// ---------------------------------------------------------------------------
__global__ void reduce_kernel() {
    int t = threadIdx.x;
    float s1 = 0.f, s2 = 0.f;
    for (int i = t; i < NN; i += 256) {
        s1 += g_T[i];
        s2 += expf(g_T[NN + i]);
    }
    __shared__ float a1[256], a2[256];
    a1[t] = s1; a2[t] = s2;
    __syncthreads();
    for (int st = 128; st; st >>= 1) {
        if (t < st) { a1[t] += a1[t + st]; a2[t] += a2[t + st]; }
        __syncthreads();
    }
    if (t == 0) {
        float mi = a1[0] / (float)NN - (a2[0] / (float)NN + logf(2.0f));
        g_const = 1.0f + 0.01f * mi;
    }
}

// ---------------------------------------------------------------------------
// Kernel 9: DIST.  out[i][j] = g_const - <x1n_i, x2n_j>
// Round-1 proven geometry (128x128 tile, BK=64, 8 warps 4m x 2n, XOR swizzle,
// 2 CTAs/SM) + 2-stage cp.async pipeline to hide L2 load latency.
// ---------------------------------------------------------------------------
#define DBM 128
#define DBN 128
#define DBK 64
#define TILE_B (DBM * DBK * 2)              // 16384 B per operand per stage
#define STAGE_B (2 * TILE_B)                // A+B per stage = 32768 B
#define DSMEM_TOTAL (2 * STAGE_B)           // 65536 B

__global__ void __launch_bounds__(256, 2)
dist_kernel(float* __restrict__ outf) {
    extern __shared__ char smem[];
    const uint32_t sb = smem_u32(smem);

    const int t    = threadIdx.x;
    const int warp = t >> 5;
    const int lane = t & 31;
    const int bm   = blockIdx.y * DBM;
    const int bn   = blockIdx.x * DBN;
    const int wm   = (warp >> 1) * 32;
    const int wn   = (warp & 1) * 64;

    const __nv_bfloat16* A = g_norm;                    // [8192][256]
    const __nv_bfloat16* B = g_norm + (size_t)NN * DD;  // [8192][256]

    float acc[2][8][4];
    #pragma unroll
    for (int i = 0; i < 2; i++)
        #pragma unroll
        for (int j = 0; j < 8; j++)
            #pragma unroll
            for (int r = 0; r < 4; r++) acc[i][j][r] = 0.f;

    // stage loader: A 128x64 + B 128x64, XOR-swizzled, 4+4 cp.async16/thread
    auto load_stage = [&](int s, int kc) {
        uint32_t base = sb + s * STAGE_B;
        #pragma unroll
        for (int i = 0; i < 4; i++) {
            int idx = t + i * 256;
            int row = idx >> 3;
            int ch  = idx & 7;
            int sw  = (ch ^ (row & 7)) * 8;
            cp_async16(base + (uint32_t)(row * DBK + sw) * 2u,
                       A + (size_t)(bm + row) * DD + kc + ch * 8);
            cp_async16(base + TILE_B + (uint32_t)(row * DBK + sw) * 2u,
                       B + (size_t)(bn + row) * DD + kc + ch * 8);
        }
    };

    // prologue: both stages in flight
    load_stage(0, 0);
    CP_COMMIT();
    load_stage(1, DBK);
    CP_COMMIT();

    const int NCHUNK = DD / DBK;            // 4
    #pragma unroll 1
    for (int c = 0; c < NCHUNK; c++) {
        if (c == NCHUNK - 1) { CP_WAIT(0); } else { CP_WAIT(1); }
        __syncthreads();

        const uint32_t aS = sb + (c & 1) * STAGE_B;
        const uint32_t bS = aS + TILE_B;

        #pragma unroll
        for (int ks = 0; ks < DBK / 16; ks++) {
            uint32_t a[2][4];
            #pragma unroll
            for (int mt = 0; mt < 2; mt++) {
                int r = wm + mt * 16 + (lane & 15);
                int cx = (ks * 2 + (lane >> 4)) ^ (r & 7);
                ldsm_x4(a[mt][0], a[mt][1], a[mt][2], a[mt][3],
                        aS + (uint32_t)(r * DBK + cx * 8) * 2u);
            }
            uint32_t b[4][4];
            #pragma unroll
            for (int bt = 0; bt < 4; bt++) {
                int nr = wn + bt * 16 + ((lane >> 4) * 8) + (lane & 7);
                int kh = (lane >> 3) & 1;
                int cx = (ks * 2 + kh) ^ (nr & 7);
                ldsm_x4(b[bt][0], b[bt][1], b[bt][2], b[bt][3],
                        bS + (uint32_t)(nr * DBK + cx * 8) * 2u);
            }
            #pragma unroll
            for (int mt = 0; mt < 2; mt++)
                #pragma unroll
                for (int nt = 0; nt < 8; nt++)
                    mma16816(acc[mt][nt], a[mt],
                             b[nt >> 1][(nt & 1) * 2],
                             b[nt >> 1][(nt & 1) * 2 + 1]);
        }

        __syncthreads();
        if (c + 2 < NCHUNK) {
            load_stage(c & 1, (c + 2) * DBK);
            CP_COMMIT();
        }
    }

    // epilogue: out = g_const - acc (direct coalesced float2 stores)
    const float cadd = g_const;
    #pragma unroll
    for (int mt = 0; mt < 2; mt++) {
        #pragma unroll
        for (int nt = 0; nt < 8; nt++) {
            int row = bm + wm + mt * 16 + (lane >> 2);
            int col = bn + wn + nt * 8 + (lane & 3) * 2;
            float* c = acc[mt][nt];
            float2 v0 = make_float2(cadd - c[0], cadd - c[1]);
            float2 v1 = make_float2(cadd - c[2], cadd - c[3]);
            *reinterpret_cast<float2*>(outf + (size_t)row * MM + col)       = v0;
            *reinterpret_cast<float2*>(outf + (size_t)(row + 8) * MM + col) = v1;
        }
    }
}

// ---------------------------------------------------------------------------
// kernel_launch
// ---------------------------------------------------------------------------
extern "C" void kernel_launch(void* const* d_in, const int* in_sizes, int n_in,
                              void* d_out, int out_size) {
    const float* x1   = (const float*)d_in[0];
    const float* x2   = (const float*)d_in[1];
    const float* Wc   = (const float*)d_in[2];
    const float* bc   = (const float*)d_in[3];
    const float* W1   = (const float*)d_in[4];
    const float* b1   = (const float*)d_in[5];
    const float* W2   = (const float*)d_in[6];
    const float* b2   = (const float*)d_in[7];
    const float* W3   = (const float*)d_in[8];
    const float* b3   = (const float*)d_in[9];
    const int*   perm = (const int*)d_in[10];
    float* out = (float*)d_out;

    cudaFuncSetAttribute(dist_kernel,
                         cudaFuncAttributeMaxDynamicSharedMemorySize, DSMEM_TOTAL);

    // 1. normalize rows + raw bf16 copies
    prep_kernel<<<NROWS, 256>>>(x1, x2);
    // 2. weight transposes to bf16
    transp_kernel<<<(2 * CC * DD + HH * HH + 255) / 256, 256>>>(Wc, W1, W2);
    // 3. compressor: xc = x @ Wc + bc   [16384 x 128]
    gemm_k<1><<<dim3(1, NROWS / BM), 256>>>(bc);
    // 4. critic inputs (joint + shuffled)
    gather_kernel<<<NROWS / 8, 256>>>(perm);
    // 5. H1 = relu(Z @ W1 + b1)
    gemm_k<2><<<dim3(1, NROWS / BM), 256>>>(b1);
    // 6. H2 = relu(H1 @ W2 + b2)
    gemm_k<3><<<dim3(1, NROWS / BM), 256>>>(b2);
    // 7. t = H2 @ W3 + b3
    tdot_kernel<<<NROWS / 8, 256>>>(W3, b3);
    // 8. mi scalar -> g_const
    reduce_kernel<<<1, 256>>>();
    // 9. distances + lambda*mi
    dist_kernel<<<dim3(MM / DBN, NN / DBM), 256, DSMEM_TOTAL>>>(out);
}